// round 1
// baseline (speedup 1.0000x reference)
#include <cuda_runtime.h>
#include <cuda_fp16.h>

#define SEQ 1024
#define NB  4

// fp16 q/k scratch (allocation-free: __device__ globals)
__device__ __half q_buf[NB * SEQ * 8];
__device__ __half k_buf[NB * SEQ * 8];

// ---------------------------------------------------------------------------
// Kernel A: mvlinear (both projections) + bias + LayerNorm + fp16 cast.
// One warp per output row n. Lanes split the m-contraction (1024 / 32 = 32
// iterations). 64 accumulators per lane: {q,k} x {4 batches} x {8 comps}.
// ---------------------------------------------------------------------------
__global__ void __launch_bounds__(128) proj_ln_kernel(
    const float* __restrict__ x,     // [4,1024,8]
    const float* __restrict__ Wq,    // [1024,1024,4]
    const float* __restrict__ bq,    // [1024]
    const float* __restrict__ Wk,    // [1024,1024,4]
    const float* __restrict__ bk,    // [1024]
    const float* __restrict__ gamma, // [8]
    const float* __restrict__ beta)  // [8]
{
    const int warp = threadIdx.x >> 5;
    const int lane = threadIdx.x & 31;
    const int n = blockIdx.x * 4 + warp;

    float aq[4][8];
    float ak[4][8];
#pragma unroll
    for (int b = 0; b < 4; b++) {
#pragma unroll
        for (int i = 0; i < 8; i++) { aq[b][i] = 0.0f; ak[b][i] = 0.0f; }
    }

    const float4* wq4 = reinterpret_cast<const float4*>(Wq) + (size_t)n * SEQ;
    const float4* wk4 = reinterpret_cast<const float4*>(Wk) + (size_t)n * SEQ;
    const float4* x4  = reinterpret_cast<const float4*>(x);

#pragma unroll 4
    for (int mi = 0; mi < 32; mi++) {
        const int m = (mi << 5) + lane;
        const float4 wq = wq4[m];   // W[n][m][0..3]  (per-grade weights)
        const float4 wk = wk4[m];
#pragma unroll
        for (int b = 0; b < 4; b++) {
            const float4 x0 = x4[(b * SEQ + m) * 2];
            const float4 x1 = x4[(b * SEQ + m) * 2 + 1];
            // grade map: i=0 -> w.x ; i=1..3 -> w.y ; i=4..6 -> w.z ; i=7 -> w.w
            aq[b][0] = fmaf(wq.x, x0.x, aq[b][0]);
            aq[b][1] = fmaf(wq.y, x0.y, aq[b][1]);
            aq[b][2] = fmaf(wq.y, x0.z, aq[b][2]);
            aq[b][3] = fmaf(wq.y, x0.w, aq[b][3]);
            aq[b][4] = fmaf(wq.z, x1.x, aq[b][4]);
            aq[b][5] = fmaf(wq.z, x1.y, aq[b][5]);
            aq[b][6] = fmaf(wq.z, x1.z, aq[b][6]);
            aq[b][7] = fmaf(wq.w, x1.w, aq[b][7]);

            ak[b][0] = fmaf(wk.x, x0.x, ak[b][0]);
            ak[b][1] = fmaf(wk.y, x0.y, ak[b][1]);
            ak[b][2] = fmaf(wk.y, x0.z, ak[b][2]);
            ak[b][3] = fmaf(wk.y, x0.w, ak[b][3]);
            ak[b][4] = fmaf(wk.z, x1.x, ak[b][4]);
            ak[b][5] = fmaf(wk.z, x1.y, ak[b][5]);
            ak[b][6] = fmaf(wk.z, x1.z, ak[b][6]);
            ak[b][7] = fmaf(wk.w, x1.w, ak[b][7]);
        }
    }

    // Warp tree-reduce all 64 accumulators to lane 0.
#pragma unroll
    for (int off = 16; off; off >>= 1) {
#pragma unroll
        for (int b = 0; b < 4; b++) {
#pragma unroll
            for (int i = 0; i < 8; i++) {
                aq[b][i] += __shfl_down_sync(0xffffffffu, aq[b][i], off);
                ak[b][i] += __shfl_down_sync(0xffffffffu, ak[b][i], off);
            }
        }
    }

    if (lane == 0) {
        float g[8], be[8];
#pragma unroll
        for (int i = 0; i < 8; i++) { g[i] = gamma[i]; be[i] = beta[i]; }
        const float biasq = bq[n];
        const float biask = bk[n];

#pragma unroll
        for (int b = 0; b < 4; b++) {
            aq[b][0] += biasq;   // bias on scalar component, BEFORE layernorm
            ak[b][0] += biask;

            // --- LayerNorm + fp16 cast, q ---
            {
                float mu = 0.0f;
#pragma unroll
                for (int i = 0; i < 8; i++) mu += aq[b][i];
                mu *= 0.125f;
                float var = 0.0f;
#pragma unroll
                for (int i = 0; i < 8; i++) { float d = aq[b][i] - mu; var = fmaf(d, d, var); }
                var *= 0.125f;
                const float r = rsqrtf(var + 1e-5f);
                __half2* dst = reinterpret_cast<__half2*>(&q_buf[((size_t)b * SEQ + n) * 8]);
#pragma unroll
                for (int j = 0; j < 4; j++) {
                    float v0 = (aq[b][2 * j]     - mu) * r * g[2 * j]     + be[2 * j];
                    float v1 = (aq[b][2 * j + 1] - mu) * r * g[2 * j + 1] + be[2 * j + 1];
                    dst[j] = __floats2half2_rn(v0, v1);
                }
            }
            // --- LayerNorm + fp16 cast, k ---
            {
                float mu = 0.0f;
#pragma unroll
                for (int i = 0; i < 8; i++) mu += ak[b][i];
                mu *= 0.125f;
                float var = 0.0f;
#pragma unroll
                for (int i = 0; i < 8; i++) { float d = ak[b][i] - mu; var = fmaf(d, d, var); }
                var *= 0.125f;
                const float r = rsqrtf(var + 1e-5f);
                __half2* dst = reinterpret_cast<__half2*>(&k_buf[((size_t)b * SEQ + n) * 8]);
#pragma unroll
                for (int j = 0; j < 4; j++) {
                    float v0 = (ak[b][2 * j]     - mu) * r * g[2 * j]     + be[2 * j];
                    float v1 = (ak[b][2 * j + 1] - mu) * r * g[2 * j + 1] + be[2 * j + 1];
                    dst[j] = __floats2half2_rn(v0, v1);
                }
            }
        }
    }
}

// ---------------------------------------------------------------------------
// Kernel B: pairwise geometric product out[b,n,m,:] = GP(q[b,n,:], k[b,m,:])
// for Cl(3,0), basis order [1, e1, e2, e3, e12, e13, e23, e123].
// Grid: (128 n-tiles, 4 batches), 512 threads. k-row staged in smem.
// Result rounded to fp16 (reference einsum dtype), stored as fp32.
// ---------------------------------------------------------------------------
__global__ void __launch_bounds__(512) gp_kernel(float* __restrict__ out)
{
    __shared__ uint4 ks[SEQ];     // k[b][m][0..7] as 8 halves = 16B
    __shared__ float qs[8][8];

    const int b  = blockIdx.y;
    const int n0 = blockIdx.x * 8;
    const int t  = threadIdx.x;

    const uint4* kb = reinterpret_cast<const uint4*>(k_buf) + (size_t)b * SEQ;
    ks[t]       = kb[t];
    ks[t + 512] = kb[t + 512];
    if (t < 64) {
        qs[t >> 3][t & 7] =
            __half2float(q_buf[(((size_t)b * SEQ) + n0 + (t >> 3)) * 8 + (t & 7)]);
    }
    __syncthreads();

#pragma unroll 1
    for (int nl = 0; nl < 8; nl++) {
        const float q0 = qs[nl][0], q1 = qs[nl][1], q2 = qs[nl][2], q3 = qs[nl][3];
        const float q4 = qs[nl][4], q5 = qs[nl][5], q6 = qs[nl][6], q7 = qs[nl][7];
        float* ob = out + ((size_t)(b * SEQ + n0 + nl)) * SEQ * 8;

#pragma unroll
        for (int rep = 0; rep < 2; rep++) {
            const int m = rep * 512 + t;
            const uint4 kv = ks[m];
            const float2 f01 = __half22float2(*reinterpret_cast<const __half2*>(&kv.x));
            const float2 f23 = __half22float2(*reinterpret_cast<const __half2*>(&kv.y));
            const float2 f45 = __half22float2(*reinterpret_cast<const __half2*>(&kv.z));
            const float2 f67 = __half22float2(*reinterpret_cast<const __half2*>(&kv.w));
            const float K0 = f01.x, K1 = f01.y, K2 = f23.x, K3 = f23.y;
            const float K4 = f45.x, K5 = f45.y, K6 = f67.x, K7 = f67.y;

            // Cl(3,0) geometric product, 64 signed terms (hand-verified table)
            const float o0 = q0*K0 + q1*K1 + q2*K2 + q3*K3 - q4*K4 - q5*K5 - q6*K6 - q7*K7;
            const float o1 = q0*K1 + q1*K0 - q2*K4 - q3*K5 + q4*K2 + q5*K3 - q6*K7 - q7*K6;
            const float o2 = q0*K2 + q1*K4 + q2*K0 - q3*K6 - q4*K1 + q5*K7 + q6*K3 + q7*K5;
            const float o3 = q0*K3 + q1*K5 + q2*K6 + q3*K0 - q4*K7 - q5*K1 - q6*K2 - q7*K4;
            const float o4 = q0*K4 + q1*K2 - q2*K1 + q3*K7 + q4*K0 - q5*K6 + q6*K5 + q7*K3;
            const float o5 = q0*K5 + q1*K3 - q2*K7 - q3*K1 + q4*K6 + q5*K0 - q6*K4 - q7*K2;
            const float o6 = q0*K6 + q1*K7 + q2*K3 - q3*K2 - q4*K5 + q5*K4 + q6*K0 + q7*K1;
            const float o7 = q0*K7 + q1*K6 - q2*K5 + q3*K4 + q4*K3 - q5*K2 + q6*K1 + q7*K0;

            // Round to fp16 (reference einsum output dtype), store as fp32.
            const float2 g01 = __half22float2(__floats2half2_rn(o0, o1));
            const float2 g23 = __half22float2(__floats2half2_rn(o2, o3));
            const float2 g45 = __half22float2(__floats2half2_rn(o4, o5));
            const float2 g67 = __half22float2(__floats2half2_rn(o6, o7));

            float4* dst = reinterpret_cast<float4*>(ob + (size_t)m * 8);
            dst[0] = make_float4(g01.x, g01.y, g23.x, g23.y);
            dst[1] = make_float4(g45.x, g45.y, g67.x, g67.y);
        }
    }
}

extern "C" void kernel_launch(void* const* d_in, const int* in_sizes, int n_in,
                              void* d_out, int out_size)
{
    (void)in_sizes; (void)n_in; (void)out_size;
    const float* x     = (const float*)d_in[0];
    const float* Wq    = (const float*)d_in[1];
    const float* bq    = (const float*)d_in[2];
    const float* Wk    = (const float*)d_in[3];
    const float* bk    = (const float*)d_in[4];
    const float* gamma = (const float*)d_in[5];
    const float* beta  = (const float*)d_in[6];
    float* out = (float*)d_out;

    proj_ln_kernel<<<256, 128>>>(x, Wq, bq, Wk, bk, gamma, beta);
    gp_kernel<<<dim3(128, NB), 512>>>(out);
}

// round 3
// speedup vs baseline: 1.1754x; 1.1754x over previous
#include <cuda_runtime.h>
#include <cuda_fp16.h>
#include <cstdint>

#define SEQ 1024

// fp16 q/k scratch (allocation-free: __device__ globals)
__device__ __half q_buf[4 * SEQ * 8];
__device__ __half k_buf[4 * SEQ * 8];

typedef unsigned long long ull;

// ---- packed f32x2 helpers (Blackwell) ----
__device__ __forceinline__ ull pk2(float lo, float hi) {
    ull d;
    asm("mov.b64 %0, {%1, %2};" : "=l"(d)
        : "r"(__float_as_uint(lo)), "r"(__float_as_uint(hi)));
    return d;
}
__device__ __forceinline__ void upk2(ull d, float& lo, float& hi) {
    unsigned a, b;
    asm("mov.b64 {%0, %1}, %2;" : "=r"(a), "=r"(b) : "l"(d));
    lo = __uint_as_float(a); hi = __uint_as_float(b);
}
__device__ __forceinline__ ull f2fma(ull a, ull b, ull c) {
    ull d;
    asm("fma.rn.f32x2 %0, %1, %2, %3;" : "=l"(d) : "l"(a), "l"(b), "l"(c));
    return d;
}
__device__ __forceinline__ ull f2mul(ull a, ull b) {
    ull d;
    asm("mul.rn.f32x2 %0, %1, %2;" : "=l"(d) : "l"(a), "l"(b));
    return d;
}

// ---------------------------------------------------------------------------
// Kernel A: mvlinear (q & k) + bias + LayerNorm + fp16 cast.
// Warp = (proj, m-half) for one n; 4 warps/block, 1024 blocks (one per n).
// 32 accumulators per lane ({4 batches} x {8 comps}); butterfly transpose-
// reduce leaves lane l holding component v = l.
// ---------------------------------------------------------------------------
__global__ void __launch_bounds__(128) proj_ln_kernel(
    const float* __restrict__ x,     // [4,1024,8]
    const float* __restrict__ Wq,    // [1024,1024,4]
    const float* __restrict__ bq,    // [1024]
    const float* __restrict__ Wk,    // [1024,1024,4]
    const float* __restrict__ bk,    // [1024]
    const float* __restrict__ gamma, // [8]
    const float* __restrict__ beta)  // [8]
{
    __shared__ float sred[4][32];

    const int w    = threadIdx.x >> 5;
    const int lane = threadIdx.x & 31;
    const int proj = w & 1;            // 0 = q, 1 = k
    const int mh   = (w >> 1) & 1;     // m-half
    const int n    = blockIdx.x;

    const float4* Wrow = reinterpret_cast<const float4*>(proj ? Wk : Wq) + (size_t)n * SEQ;
    const float4* x4   = reinterpret_cast<const float4*>(x);

    float acc[32];
#pragma unroll
    for (int v = 0; v < 32; v++) acc[v] = 0.0f;

    const int mbase = mh * 512 + lane;
#pragma unroll 4
    for (int mi = 0; mi < 16; mi++) {
        const int m = mbase + mi * 32;
        const float4 wv = __ldg(&Wrow[m]);
#pragma unroll
        for (int b = 0; b < 4; b++) {
            const float4 x0 = __ldg(&x4[(b * SEQ + m) * 2]);
            const float4 x1 = __ldg(&x4[(b * SEQ + m) * 2 + 1]);
            acc[b * 8 + 0] = fmaf(wv.x, x0.x, acc[b * 8 + 0]);
            acc[b * 8 + 1] = fmaf(wv.y, x0.y, acc[b * 8 + 1]);
            acc[b * 8 + 2] = fmaf(wv.y, x0.z, acc[b * 8 + 2]);
            acc[b * 8 + 3] = fmaf(wv.y, x0.w, acc[b * 8 + 3]);
            acc[b * 8 + 4] = fmaf(wv.z, x1.x, acc[b * 8 + 4]);
            acc[b * 8 + 5] = fmaf(wv.z, x1.y, acc[b * 8 + 5]);
            acc[b * 8 + 6] = fmaf(wv.z, x1.z, acc[b * 8 + 6]);
            acc[b * 8 + 7] = fmaf(wv.w, x1.w, acc[b * 8 + 7]);
        }
    }

    // Butterfly transpose-reduce: 31 shuffles; lane l ends with value index l.
#pragma unroll
    for (int off = 16; off; off >>= 1) {
        const bool up = (lane & off) != 0;
#pragma unroll
        for (int k = 0; k < off; k++) {
            float send  = up ? acc[k] : acc[k + off];
            float other = __shfl_xor_sync(0xffffffffu, send, off);
            acc[k] = (up ? acc[k + off] : acc[k]) + other;
        }
    }
    sred[w][lane] = acc[0];
    __syncthreads();

    const int t = threadIdx.x;
    if (t < 8) {
        const int b  = t & 3;
        const int pj = (t >> 2) & 1;
        float v[8];
#pragma unroll
        for (int i = 0; i < 8; i++)
            v[i] = sred[pj][b * 8 + i] + sred[pj + 2][b * 8 + i];
        v[0] += pj ? bk[n] : bq[n];   // bias on scalar comp, before LN

        float mu = 0.0f;
#pragma unroll
        for (int i = 0; i < 8; i++) mu += v[i];
        mu *= 0.125f;
        float var = 0.0f;
#pragma unroll
        for (int i = 0; i < 8; i++) { float d = v[i] - mu; var = fmaf(d, d, var); }
        const float r = rsqrtf(var * 0.125f + 1e-5f);

        __half2* dst = reinterpret_cast<__half2*>(
            (pj ? k_buf : q_buf) + ((size_t)b * SEQ + n) * 8);
#pragma unroll
        for (int j = 0; j < 4; j++) {
            float a0 = (v[2 * j]     - mu) * r * gamma[2 * j]     + beta[2 * j];
            float a1 = (v[2 * j + 1] - mu) * r * gamma[2 * j + 1] + beta[2 * j + 1];
            dst[j] = __floats2half2_rn(a0, a1);
        }
    }
}

// ---------------------------------------------------------------------------
// Kernel B: geometric product out[b,n,m,:] = GP(q[b,n], k[b,m]), Cl(3,0),
// basis [1, e1, e2, e3, e12, e13, e23, e123].
// Thread handles two m values (m0, m0+256) packed in f32x2 lanes. K converted
// once per thread into 8 packed regs. q broadcast from a tiny smem tile.
// Output rounded to fp16 (reference einsum dtype), stored fp32.
// ---------------------------------------------------------------------------
__global__ void __launch_bounds__(256) gp_kernel(float* __restrict__ out)
{
    __shared__ float qs[8][8];

    const int b     = blockIdx.y;
    const int ntile = blockIdx.x >> 1;
    const int mh    = blockIdx.x & 1;
    const int n0    = ntile * 8;
    const int t     = threadIdx.x;
    const int m0    = mh * 512 + t;
    const int m1    = m0 + 256;

    if (t < 64)
        qs[t >> 3][t & 7] =
            __half2float(q_buf[((size_t)b * SEQ + n0 + (t >> 3)) * 8 + (t & 7)]);

    const uint4* kb4 = reinterpret_cast<const uint4*>(k_buf) + (size_t)b * SEQ;
    const uint4 kv0 = __ldg(&kb4[m0]);
    const uint4 kv1 = __ldg(&kb4[m1]);

    float A[8], B[8];
    {
        float2 f;
        f = __half22float2(*reinterpret_cast<const __half2*>(&kv0.x)); A[0]=f.x; A[1]=f.y;
        f = __half22float2(*reinterpret_cast<const __half2*>(&kv0.y)); A[2]=f.x; A[3]=f.y;
        f = __half22float2(*reinterpret_cast<const __half2*>(&kv0.z)); A[4]=f.x; A[5]=f.y;
        f = __half22float2(*reinterpret_cast<const __half2*>(&kv0.w)); A[6]=f.x; A[7]=f.y;
        f = __half22float2(*reinterpret_cast<const __half2*>(&kv1.x)); B[0]=f.x; B[1]=f.y;
        f = __half22float2(*reinterpret_cast<const __half2*>(&kv1.y)); B[2]=f.x; B[3]=f.y;
        f = __half22float2(*reinterpret_cast<const __half2*>(&kv1.z)); B[4]=f.x; B[5]=f.y;
        f = __half22float2(*reinterpret_cast<const __half2*>(&kv1.w)); B[6]=f.x; B[7]=f.y;
    }
    ull K0 = pk2(A[0], B[0]), K1 = pk2(A[1], B[1]), K2 = pk2(A[2], B[2]),
        K3 = pk2(A[3], B[3]), K4 = pk2(A[4], B[4]), K5 = pk2(A[5], B[5]),
        K6 = pk2(A[6], B[6]), K7 = pk2(A[7], B[7]);

    __syncthreads();

#pragma unroll 1
    for (int nl = 0; nl < 8; nl++) {
        const float q0 = qs[nl][0], q1 = qs[nl][1], q2 = qs[nl][2], q3 = qs[nl][3];
        const float q4 = qs[nl][4], q5 = qs[nl][5], q6 = qs[nl][6], q7 = qs[nl][7];

        ull a0, a1, a2, a3, a4, a5, a6, a7;
        { // i=0: all +, sigma = identity
            const ull P = pk2(q0, q0);
            a0 = f2mul(P, K0); a1 = f2mul(P, K1); a2 = f2mul(P, K2); a3 = f2mul(P, K3);
            a4 = f2mul(P, K4); a5 = f2mul(P, K5); a6 = f2mul(P, K6); a7 = f2mul(P, K7);
        }
        { // i=1: all +; K: 1,0,4,5,2,3,7,6
            const ull P = pk2(q1, q1);
            a0 = f2fma(P, K1, a0); a1 = f2fma(P, K0, a1); a2 = f2fma(P, K4, a2); a3 = f2fma(P, K5, a3);
            a4 = f2fma(P, K2, a4); a5 = f2fma(P, K3, a5); a6 = f2fma(P, K7, a6); a7 = f2fma(P, K6, a7);
        }
        { // i=2: + - + + - - + -; K: 2,4,0,6,1,7,3,5
            const ull P = pk2(q2, q2), N = pk2(-q2, -q2);
            a0 = f2fma(P, K2, a0); a1 = f2fma(N, K4, a1); a2 = f2fma(P, K0, a2); a3 = f2fma(P, K6, a3);
            a4 = f2fma(N, K1, a4); a5 = f2fma(N, K7, a5); a6 = f2fma(P, K3, a6); a7 = f2fma(N, K5, a7);
        }
        { // i=3: + - - + + - - +; K: 3,5,6,0,7,1,2,4
            const ull P = pk2(q3, q3), N = pk2(-q3, -q3);
            a0 = f2fma(P, K3, a0); a1 = f2fma(N, K5, a1); a2 = f2fma(N, K6, a2); a3 = f2fma(P, K0, a3);
            a4 = f2fma(P, K7, a4); a5 = f2fma(N, K1, a5); a6 = f2fma(N, K2, a6); a7 = f2fma(P, K4, a7);
        }
        { // i=4: - + - - + + - +; K: 4,2,1,7,0,6,5,3
            const ull P = pk2(q4, q4), N = pk2(-q4, -q4);
            a0 = f2fma(N, K4, a0); a1 = f2fma(P, K2, a1); a2 = f2fma(N, K1, a2); a3 = f2fma(N, K7, a3);
            a4 = f2fma(P, K0, a4); a5 = f2fma(P, K6, a5); a6 = f2fma(N, K5, a6); a7 = f2fma(P, K3, a7);
        }
        { // i=5: - + + - - + + -; K: 5,3,7,1,6,0,4,2
            const ull P = pk2(q5, q5), N = pk2(-q5, -q5);
            a0 = f2fma(N, K5, a0); a1 = f2fma(P, K3, a1); a2 = f2fma(P, K7, a2); a3 = f2fma(N, K1, a3);
            a4 = f2fma(N, K6, a4); a5 = f2fma(P, K0, a5); a6 = f2fma(P, K4, a6); a7 = f2fma(N, K2, a7);
        }
        { // i=6: - - + - + - + +; K: 6,7,3,2,5,4,0,1
            const ull P = pk2(q6, q6), N = pk2(-q6, -q6);
            a0 = f2fma(N, K6, a0); a1 = f2fma(N, K7, a1); a2 = f2fma(P, K3, a2); a3 = f2fma(N, K2, a3);
            a4 = f2fma(P, K5, a4); a5 = f2fma(N, K4, a5); a6 = f2fma(P, K0, a6); a7 = f2fma(P, K1, a7);
        }
        { // i=7: - - + - + - + +; K: 7,6,5,4,3,2,1,0   (e123*e12 = -e3 -> a3 NEGATIVE)
            const ull P = pk2(q7, q7), N = pk2(-q7, -q7);
            a0 = f2fma(N, K7, a0); a1 = f2fma(N, K6, a1); a2 = f2fma(P, K5, a2); a3 = f2fma(N, K4, a3);
            a4 = f2fma(P, K3, a4); a5 = f2fma(N, K2, a5); a6 = f2fma(P, K1, a6); a7 = f2fma(P, K0, a7);
        }

        float l0,l1,l2,l3,l4,l5,l6,l7, h0,h1,h2,h3,h4,h5,h6,h7;
        upk2(a0, l0, h0); upk2(a1, l1, h1); upk2(a2, l2, h2); upk2(a3, l3, h3);
        upk2(a4, l4, h4); upk2(a5, l5, h5); upk2(a6, l6, h6); upk2(a7, l7, h7);

        float* ob = out + ((size_t)(b * SEQ + n0 + nl)) * SEQ * 8;

        {   // m0: round to fp16, store fp32
            const float2 r01 = __half22float2(__floats2half2_rn(l0, l1));
            const float2 r23 = __half22float2(__floats2half2_rn(l2, l3));
            const float2 r45 = __half22float2(__floats2half2_rn(l4, l5));
            const float2 r67 = __half22float2(__floats2half2_rn(l6, l7));
            float4* d = reinterpret_cast<float4*>(ob + (size_t)m0 * 8);
            d[0] = make_float4(r01.x, r01.y, r23.x, r23.y);
            d[1] = make_float4(r45.x, r45.y, r67.x, r67.y);
        }
        {   // m1
            const float2 r01 = __half22float2(__floats2half2_rn(h0, h1));
            const float2 r23 = __half22float2(__floats2half2_rn(h2, h3));
            const float2 r45 = __half22float2(__floats2half2_rn(h4, h5));
            const float2 r67 = __half22float2(__floats2half2_rn(h6, h7));
            float4* d = reinterpret_cast<float4*>(ob + (size_t)m1 * 8);
            d[0] = make_float4(r01.x, r01.y, r23.x, r23.y);
            d[1] = make_float4(r45.x, r45.y, r67.x, r67.y);
        }
    }
}

extern "C" void kernel_launch(void* const* d_in, const int* in_sizes, int n_in,
                              void* d_out, int out_size)
{
    (void)in_sizes; (void)n_in; (void)out_size;
    const float* x     = (const float*)d_in[0];
    const float* Wq    = (const float*)d_in[1];
    const float* bq    = (const float*)d_in[2];
    const float* Wk    = (const float*)d_in[3];
    const float* bk    = (const float*)d_in[4];
    const float* gamma = (const float*)d_in[5];
    const float* beta  = (const float*)d_in[6];
    float* out = (float*)d_out;

    proj_ln_kernel<<<1024, 128>>>(x, Wq, bq, Wk, bk, gamma, beta);
    gp_kernel<<<dim3(256, 4), 256>>>(out);
}

// round 4
// speedup vs baseline: 1.2138x; 1.0327x over previous
#include <cuda_runtime.h>
#include <cuda_fp16.h>
#include <cstdint>

#define SEQ 1024

// fp16 q/k scratch (allocation-free: __device__ globals)
__device__ __half q_buf[4 * SEQ * 8];
__device__ __half k_buf[4 * SEQ * 8];

typedef unsigned long long ull;

// ---- packed f32x2 helpers (Blackwell) ----
__device__ __forceinline__ ull pk2(float lo, float hi) {
    ull d;
    asm("mov.b64 %0, {%1, %2};" : "=l"(d)
        : "r"(__float_as_uint(lo)), "r"(__float_as_uint(hi)));
    return d;
}
__device__ __forceinline__ void upk2(ull d, float& lo, float& hi) {
    unsigned a, b;
    asm("mov.b64 {%0, %1}, %2;" : "=r"(a), "=r"(b) : "l"(d));
    lo = __uint_as_float(a); hi = __uint_as_float(b);
}
__device__ __forceinline__ ull f2fma(ull a, ull b, ull c) {
    ull d;
    asm("fma.rn.f32x2 %0, %1, %2, %3;" : "=l"(d) : "l"(a), "l"(b), "l"(c));
    return d;
}
__device__ __forceinline__ ull f2mul(ull a, ull b) {
    ull d;
    asm("mul.rn.f32x2 %0, %1, %2;" : "=l"(d) : "l"(a), "l"(b));
    return d;
}

// ---------------------------------------------------------------------------
// Kernel A: mvlinear (q & k) + bias + LayerNorm + fp16 cast.
// Block = one n; 8 warps = (proj 0/1) x (m-quarter 0..3). Fully unrolled
// 8 iterations -> ~8 W loads in flight per warp (DRAM MLP). Butterfly
// transpose-reduce leaves lane l holding component index l.
// ---------------------------------------------------------------------------
__global__ void __launch_bounds__(256) proj_ln_kernel(
    const float* __restrict__ x,     // [4,1024,8]
    const float* __restrict__ Wq,    // [1024,1024,4]
    const float* __restrict__ bq,    // [1024]
    const float* __restrict__ Wk,    // [1024,1024,4]
    const float* __restrict__ bk,    // [1024]
    const float* __restrict__ gamma, // [8]
    const float* __restrict__ beta)  // [8]
{
    __shared__ float sred[8][32];

    const int w    = threadIdx.x >> 5;
    const int lane = threadIdx.x & 31;
    const int proj = w & 1;            // 0 = q, 1 = k
    const int qr   = w >> 1;           // m-quarter 0..3
    const int n    = blockIdx.x;

    const float4* Wrow = reinterpret_cast<const float4*>(proj ? Wk : Wq) + (size_t)n * SEQ;
    const float4* x4   = reinterpret_cast<const float4*>(x);

    float acc[32];
#pragma unroll
    for (int v = 0; v < 32; v++) acc[v] = 0.0f;

    const int mbase = qr * 256 + lane;
#pragma unroll
    for (int mi = 0; mi < 8; mi++) {
        const int m = mbase + mi * 32;
        const float4 wv = __ldg(&Wrow[m]);
#pragma unroll
        for (int b = 0; b < 4; b++) {
            const float4 x0 = __ldg(&x4[(b * SEQ + m) * 2]);
            const float4 x1 = __ldg(&x4[(b * SEQ + m) * 2 + 1]);
            acc[b * 8 + 0] = fmaf(wv.x, x0.x, acc[b * 8 + 0]);
            acc[b * 8 + 1] = fmaf(wv.y, x0.y, acc[b * 8 + 1]);
            acc[b * 8 + 2] = fmaf(wv.y, x0.z, acc[b * 8 + 2]);
            acc[b * 8 + 3] = fmaf(wv.y, x0.w, acc[b * 8 + 3]);
            acc[b * 8 + 4] = fmaf(wv.z, x1.x, acc[b * 8 + 4]);
            acc[b * 8 + 5] = fmaf(wv.z, x1.y, acc[b * 8 + 5]);
            acc[b * 8 + 6] = fmaf(wv.z, x1.z, acc[b * 8 + 6]);
            acc[b * 8 + 7] = fmaf(wv.w, x1.w, acc[b * 8 + 7]);
        }
    }

    // Butterfly transpose-reduce: lane l ends holding value index l.
#pragma unroll
    for (int off = 16; off; off >>= 1) {
        const bool up = (lane & off) != 0;
#pragma unroll
        for (int k = 0; k < off; k++) {
            float send  = up ? acc[k] : acc[k + off];
            float other = __shfl_xor_sync(0xffffffffu, send, off);
            acc[k] = (up ? acc[k + off] : acc[k]) + other;
        }
    }
    sred[w][lane] = acc[0];
    __syncthreads();

    const int t = threadIdx.x;
    if (t < 8) {
        const int b  = t & 3;
        const int pj = (t >> 2) & 1;
        float v[8];
#pragma unroll
        for (int i = 0; i < 8; i++)
            v[i] = (sred[pj][b * 8 + i] + sred[pj + 2][b * 8 + i])
                 + (sred[pj + 4][b * 8 + i] + sred[pj + 6][b * 8 + i]);
        v[0] += pj ? bk[n] : bq[n];   // bias on scalar comp, before LN

        float mu = 0.0f;
#pragma unroll
        for (int i = 0; i < 8; i++) mu += v[i];
        mu *= 0.125f;
        float var = 0.0f;
#pragma unroll
        for (int i = 0; i < 8; i++) { float d = v[i] - mu; var = fmaf(d, d, var); }
        const float r = rsqrtf(var * 0.125f + 1e-5f);

        __half2* dst = reinterpret_cast<__half2*>(
            (pj ? k_buf : q_buf) + ((size_t)b * SEQ + n) * 8);
#pragma unroll
        for (int j = 0; j < 4; j++) {
            float a0 = (v[2 * j]     - mu) * r * gamma[2 * j]     + beta[2 * j];
            float a1 = (v[2 * j + 1] - mu) * r * gamma[2 * j + 1] + beta[2 * j + 1];
            dst[j] = __floats2half2_rn(a0, a1);
        }
    }
}

// ---------------------------------------------------------------------------
// Kernel B: geometric product out[b,n,m,:] = GP(q[b,n], k[b,m]), Cl(3,0),
// basis [1, e1, e2, e3, e12, e13, e23, e123].
// Thread handles two ADJACENT m values (2t, 2t+1) packed in f32x2 lanes ->
// 64B contiguous stores per (thread, n-row). 4 n-rows per block, streaming
// (__stcs) fp32 stores, no output fp16 rounding (error << threshold).
// ---------------------------------------------------------------------------
__global__ void __launch_bounds__(256) gp_kernel(float* __restrict__ out)
{
    __shared__ float qs[4][8];

    const int b     = blockIdx.y;
    const int ntile = blockIdx.x >> 1;
    const int mh    = blockIdx.x & 1;
    const int n0    = ntile * 4;
    const int t     = threadIdx.x;
    const int m0    = mh * 512 + 2 * t;

    if (t < 32)
        qs[t >> 3][t & 7] =
            __half2float(q_buf[((size_t)b * SEQ + n0 + (t >> 3)) * 8 + (t & 7)]);

    const uint4* kb4 = reinterpret_cast<const uint4*>(k_buf) + (size_t)b * SEQ;
    const uint4 kv0 = __ldg(&kb4[m0]);
    const uint4 kv1 = __ldg(&kb4[m0 + 1]);

    float A[8], B[8];
    {
        float2 f;
        f = __half22float2(*reinterpret_cast<const __half2*>(&kv0.x)); A[0]=f.x; A[1]=f.y;
        f = __half22float2(*reinterpret_cast<const __half2*>(&kv0.y)); A[2]=f.x; A[3]=f.y;
        f = __half22float2(*reinterpret_cast<const __half2*>(&kv0.z)); A[4]=f.x; A[5]=f.y;
        f = __half22float2(*reinterpret_cast<const __half2*>(&kv0.w)); A[6]=f.x; A[7]=f.y;
        f = __half22float2(*reinterpret_cast<const __half2*>(&kv1.x)); B[0]=f.x; B[1]=f.y;
        f = __half22float2(*reinterpret_cast<const __half2*>(&kv1.y)); B[2]=f.x; B[3]=f.y;
        f = __half22float2(*reinterpret_cast<const __half2*>(&kv1.z)); B[4]=f.x; B[5]=f.y;
        f = __half22float2(*reinterpret_cast<const __half2*>(&kv1.w)); B[6]=f.x; B[7]=f.y;
    }
    const ull K0 = pk2(A[0], B[0]), K1 = pk2(A[1], B[1]), K2 = pk2(A[2], B[2]),
              K3 = pk2(A[3], B[3]), K4 = pk2(A[4], B[4]), K5 = pk2(A[5], B[5]),
              K6 = pk2(A[6], B[6]), K7 = pk2(A[7], B[7]);

    __syncthreads();

#pragma unroll 1
    for (int nl = 0; nl < 4; nl++) {
        const float q0 = qs[nl][0], q1 = qs[nl][1], q2 = qs[nl][2], q3 = qs[nl][3];
        const float q4 = qs[nl][4], q5 = qs[nl][5], q6 = qs[nl][6], q7 = qs[nl][7];

        ull a0, a1, a2, a3, a4, a5, a6, a7;
        { // i=0: all +
            const ull P = pk2(q0, q0);
            a0 = f2mul(P, K0); a1 = f2mul(P, K1); a2 = f2mul(P, K2); a3 = f2mul(P, K3);
            a4 = f2mul(P, K4); a5 = f2mul(P, K5); a6 = f2mul(P, K6); a7 = f2mul(P, K7);
        }
        { // i=1: all +; K: 1,0,4,5,2,3,7,6
            const ull P = pk2(q1, q1);
            a0 = f2fma(P, K1, a0); a1 = f2fma(P, K0, a1); a2 = f2fma(P, K4, a2); a3 = f2fma(P, K5, a3);
            a4 = f2fma(P, K2, a4); a5 = f2fma(P, K3, a5); a6 = f2fma(P, K7, a6); a7 = f2fma(P, K6, a7);
        }
        { // i=2: + - + + - - + -; K: 2,4,0,6,1,7,3,5
            const ull P = pk2(q2, q2), N = pk2(-q2, -q2);
            a0 = f2fma(P, K2, a0); a1 = f2fma(N, K4, a1); a2 = f2fma(P, K0, a2); a3 = f2fma(P, K6, a3);
            a4 = f2fma(N, K1, a4); a5 = f2fma(N, K7, a5); a6 = f2fma(P, K3, a6); a7 = f2fma(N, K5, a7);
        }
        { // i=3: + - - + + - - +; K: 3,5,6,0,7,1,2,4
            const ull P = pk2(q3, q3), N = pk2(-q3, -q3);
            a0 = f2fma(P, K3, a0); a1 = f2fma(N, K5, a1); a2 = f2fma(N, K6, a2); a3 = f2fma(P, K0, a3);
            a4 = f2fma(P, K7, a4); a5 = f2fma(N, K1, a5); a6 = f2fma(N, K2, a6); a7 = f2fma(P, K4, a7);
        }
        { // i=4: - + - - + + - +; K: 4,2,1,7,0,6,5,3
            const ull P = pk2(q4, q4), N = pk2(-q4, -q4);
            a0 = f2fma(N, K4, a0); a1 = f2fma(P, K2, a1); a2 = f2fma(N, K1, a2); a3 = f2fma(N, K7, a3);
            a4 = f2fma(P, K0, a4); a5 = f2fma(P, K6, a5); a6 = f2fma(N, K5, a6); a7 = f2fma(P, K3, a7);
        }
        { // i=5: - + + - - + + -; K: 5,3,7,1,6,0,4,2
            const ull P = pk2(q5, q5), N = pk2(-q5, -q5);
            a0 = f2fma(N, K5, a0); a1 = f2fma(P, K3, a1); a2 = f2fma(P, K7, a2); a3 = f2fma(N, K1, a3);
            a4 = f2fma(N, K6, a4); a5 = f2fma(P, K0, a5); a6 = f2fma(P, K4, a6); a7 = f2fma(N, K2, a7);
        }
        { // i=6: - - + - + - + +; K: 6,7,3,2,5,4,0,1
            const ull P = pk2(q6, q6), N = pk2(-q6, -q6);
            a0 = f2fma(N, K6, a0); a1 = f2fma(N, K7, a1); a2 = f2fma(P, K3, a2); a3 = f2fma(N, K2, a3);
            a4 = f2fma(P, K5, a4); a5 = f2fma(N, K4, a5); a6 = f2fma(P, K0, a6); a7 = f2fma(P, K1, a7);
        }
        { // i=7: - - + - + - + +; K: 7,6,5,4,3,2,1,0  (e123*e12 = -e3)
            const ull P = pk2(q7, q7), N = pk2(-q7, -q7);
            a0 = f2fma(N, K7, a0); a1 = f2fma(N, K6, a1); a2 = f2fma(P, K5, a2); a3 = f2fma(N, K4, a3);
            a4 = f2fma(P, K3, a4); a5 = f2fma(N, K2, a5); a6 = f2fma(P, K1, a6); a7 = f2fma(P, K0, a7);
        }

        float l0,l1,l2,l3,l4,l5,l6,l7, h0,h1,h2,h3,h4,h5,h6,h7;
        upk2(a0, l0, h0); upk2(a1, l1, h1); upk2(a2, l2, h2); upk2(a3, l3, h3);
        upk2(a4, l4, h4); upk2(a5, l5, h5); upk2(a6, l6, h6); upk2(a7, l7, h7);

        // 64B contiguous per thread: [m0 comps 0..7][m0+1 comps 0..7]
        float4* d = reinterpret_cast<float4*>(
            out + ((size_t)(b * SEQ + n0 + nl) * SEQ + m0) * 8);
        __stcs(d + 0, make_float4(l0, l1, l2, l3));
        __stcs(d + 1, make_float4(l4, l5, l6, l7));
        __stcs(d + 2, make_float4(h0, h1, h2, h3));
        __stcs(d + 3, make_float4(h4, h5, h6, h7));
    }
}

extern "C" void kernel_launch(void* const* d_in, const int* in_sizes, int n_in,
                              void* d_out, int out_size)
{
    (void)in_sizes; (void)n_in; (void)out_size;
    const float* x     = (const float*)d_in[0];
    const float* Wq    = (const float*)d_in[1];
    const float* bq    = (const float*)d_in[2];
    const float* Wk    = (const float*)d_in[3];
    const float* bk    = (const float*)d_in[4];
    const float* gamma = (const float*)d_in[5];
    const float* beta  = (const float*)d_in[6];
    float* out = (float*)d_out;

    proj_ln_kernel<<<1024, 256>>>(x, Wq, bq, Wk, bk, gamma, beta);
    gp_kernel<<<dim3(512, 4), 256>>>(out);
}

// round 5
// speedup vs baseline: 1.9526x; 1.6086x over previous
#include <cuda_runtime.h>
#include <cuda_fp16.h>
#include <cstdint>

#define SEQ 1024

// fp16 q/k scratch (allocation-free: __device__ globals)
__device__ __half q_buf[4 * SEQ * 8];
__device__ __half k_buf[4 * SEQ * 8];

typedef unsigned long long ull;

// ---- packed f32x2 helpers (Blackwell) ----
__device__ __forceinline__ ull pk2(float lo, float hi) {
    ull d;
    asm("mov.b64 %0, {%1, %2};" : "=l"(d)
        : "r"(__float_as_uint(lo)), "r"(__float_as_uint(hi)));
    return d;
}
__device__ __forceinline__ void upk2(ull d, float& lo, float& hi) {
    unsigned a, b;
    asm("mov.b64 {%0, %1}, %2;" : "=r"(a), "=r"(b) : "l"(d));
    lo = __uint_as_float(a); hi = __uint_as_float(b);
}
__device__ __forceinline__ ull f2fma(ull a, ull b, ull c) {
    ull d;
    asm("fma.rn.f32x2 %0, %1, %2, %3;" : "=l"(d) : "l"(a), "l"(b), "l"(c));
    return d;
}
__device__ __forceinline__ ull f2mul(ull a, ull b) {
    ull d;
    asm("mul.rn.f32x2 %0, %1, %2;" : "=l"(d) : "l"(a), "l"(b));
    return d;
}

// ---------------------------------------------------------------------------
// Kernel A: mvlinear (q AND k in one warp -> x loaded once for both) +
// bias + LayerNorm + fp16 cast. Block = one n; 8 warps = m-eighths (128 m,
// 4 iterations each). 64 accumulators/lane ({q,k} x {4 b} x {8 comps}).
// Two butterfly transpose-reduces leave lane l holding component index l.
// ---------------------------------------------------------------------------
__global__ void __launch_bounds__(256) proj_ln_kernel(
    const float* __restrict__ x,     // [4,1024,8]
    const float* __restrict__ Wq,    // [1024,1024,4]
    const float* __restrict__ bq,    // [1024]
    const float* __restrict__ Wk,    // [1024,1024,4]
    const float* __restrict__ bk,    // [1024]
    const float* __restrict__ gamma, // [8]
    const float* __restrict__ beta)  // [8]
{
    __shared__ float sred[8][64];

    const int w    = threadIdx.x >> 5;
    const int lane = threadIdx.x & 31;
    const int n    = blockIdx.x;

    const float4* wqr = reinterpret_cast<const float4*>(Wq) + (size_t)n * SEQ;
    const float4* wkr = reinterpret_cast<const float4*>(Wk) + (size_t)n * SEQ;
    const float4* x4  = reinterpret_cast<const float4*>(x);

    float aq[32], ak[32];
#pragma unroll
    for (int v = 0; v < 32; v++) { aq[v] = 0.0f; ak[v] = 0.0f; }

    const int mbase = w * 128 + lane;
#pragma unroll
    for (int mi = 0; mi < 4; mi++) {
        const int m = mbase + mi * 32;
        const float4 wq = __ldg(&wqr[m]);
        const float4 wk = __ldg(&wkr[m]);
#pragma unroll
        for (int b = 0; b < 4; b++) {
            const float4 x0 = __ldg(&x4[(b * SEQ + m) * 2]);
            const float4 x1 = __ldg(&x4[(b * SEQ + m) * 2 + 1]);
            aq[b*8+0] = fmaf(wq.x, x0.x, aq[b*8+0]);  ak[b*8+0] = fmaf(wk.x, x0.x, ak[b*8+0]);
            aq[b*8+1] = fmaf(wq.y, x0.y, aq[b*8+1]);  ak[b*8+1] = fmaf(wk.y, x0.y, ak[b*8+1]);
            aq[b*8+2] = fmaf(wq.y, x0.z, aq[b*8+2]);  ak[b*8+2] = fmaf(wk.y, x0.z, ak[b*8+2]);
            aq[b*8+3] = fmaf(wq.y, x0.w, aq[b*8+3]);  ak[b*8+3] = fmaf(wk.y, x0.w, ak[b*8+3]);
            aq[b*8+4] = fmaf(wq.z, x1.x, aq[b*8+4]);  ak[b*8+4] = fmaf(wk.z, x1.x, ak[b*8+4]);
            aq[b*8+5] = fmaf(wq.z, x1.y, aq[b*8+5]);  ak[b*8+5] = fmaf(wk.z, x1.y, ak[b*8+5]);
            aq[b*8+6] = fmaf(wq.z, x1.z, aq[b*8+6]);  ak[b*8+6] = fmaf(wk.z, x1.z, ak[b*8+6]);
            aq[b*8+7] = fmaf(wq.w, x1.w, aq[b*8+7]);  ak[b*8+7] = fmaf(wk.w, x1.w, ak[b*8+7]);
        }
    }

    // Butterfly transpose-reduce (x2): lane l ends holding value index l.
#pragma unroll
    for (int off = 16; off; off >>= 1) {
        const bool up = (lane & off) != 0;
#pragma unroll
        for (int k = 0; k < off; k++) {
            float sq = up ? aq[k] : aq[k + off];
            float oq = __shfl_xor_sync(0xffffffffu, sq, off);
            aq[k] = (up ? aq[k + off] : aq[k]) + oq;
            float sk = up ? ak[k] : ak[k + off];
            float ok = __shfl_xor_sync(0xffffffffu, sk, off);
            ak[k] = (up ? ak[k + off] : ak[k]) + ok;
        }
    }
    sred[w][lane]      = aq[0];
    sred[w][lane + 32] = ak[0];
    __syncthreads();

    const int t = threadIdx.x;
    if (t < 8) {
        const int b  = t & 3;
        const int pj = (t >> 2) & 1;
        float v[8];
#pragma unroll
        for (int i = 0; i < 8; i++) {
            float s = 0.0f;
#pragma unroll
            for (int ww = 0; ww < 8; ww++) s += sred[ww][pj * 32 + b * 8 + i];
            v[i] = s;
        }
        v[0] += pj ? bk[n] : bq[n];   // bias on scalar comp, before LN

        float mu = 0.0f;
#pragma unroll
        for (int i = 0; i < 8; i++) mu += v[i];
        mu *= 0.125f;
        float var = 0.0f;
#pragma unroll
        for (int i = 0; i < 8; i++) { float d = v[i] - mu; var = fmaf(d, d, var); }
        const float r = rsqrtf(var * 0.125f + 1e-5f);

        __half2* dst = reinterpret_cast<__half2*>(
            (pj ? k_buf : q_buf) + ((size_t)b * SEQ + n) * 8);
#pragma unroll
        for (int j = 0; j < 4; j++) {
            float a0 = (v[2*j]   - mu) * r * gamma[2*j]   + beta[2*j];
            float a1 = (v[2*j+1] - mu) * r * gamma[2*j+1] + beta[2*j+1];
            dst[j] = __floats2half2_rn(a0, a1);
        }
    }
}

// ---------------------------------------------------------------------------
// Kernel B: geometric product out[b,n,m,:] = GP(q[b,n], k[b,m]), Cl(3,0),
// basis [1, e1, e2, e3, e12, e13, e23, e123].
//
// Lane-parity split: even lanes compute comps 0..3, odd lanes comps 4..7 via
// the duality out o (-e123): odd lanes transform K once (signed permutation),
// run the identical 32-FMA table, and reverse order at store (SELs on alu
// pipe). Each thread covers m-pair (m_a, m_a+16) in f32x2 lanes; a warp-STG
// is 512B contiguous (ideal 4 wavefronts). 32 n-rows per block amortize the
// K load; 512 blocks = one full wave.
// ---------------------------------------------------------------------------
__global__ void __launch_bounds__(256) gp_kernel(float* __restrict__ out)
{
    __shared__ float qs[32][8];

    const int b      = blockIdx.y;
    const int ntile  = blockIdx.x >> 2;     // 0..31
    const int mchunk = blockIdx.x & 3;      // 0..3
    const int n0     = ntile * 32;
    const int t      = threadIdx.x;
    const int w      = t >> 5;
    const int lane   = t & 31;
    const int half   = lane & 1;            // 0: comps 0-3, 1: comps 4-7
    const int mm     = lane >> 1;           // 0..15
    const int m_a    = mchunk * 256 + w * 32 + mm;   // pair partner: m_a + 16

    // q tile: 32 rows x 8 comps
    qs[t >> 3][t & 7] =
        __half2float(q_buf[((size_t)b * SEQ + n0 + (t >> 3)) * 8 + (t & 7)]);

    // K for both m's of this thread
    const uint4* kb4 = reinterpret_cast<const uint4*>(k_buf) + (size_t)b * SEQ;
    const uint4 kva = __ldg(&kb4[m_a]);
    const uint4 kvb = __ldg(&kb4[m_a + 16]);

    float A[8], B[8];
    {
        float2 f;
        f = __half22float2(*reinterpret_cast<const __half2*>(&kva.x)); A[0]=f.x; A[1]=f.y;
        f = __half22float2(*reinterpret_cast<const __half2*>(&kva.y)); A[2]=f.x; A[3]=f.y;
        f = __half22float2(*reinterpret_cast<const __half2*>(&kva.z)); A[4]=f.x; A[5]=f.y;
        f = __half22float2(*reinterpret_cast<const __half2*>(&kva.w)); A[6]=f.x; A[7]=f.y;
        f = __half22float2(*reinterpret_cast<const __half2*>(&kvb.x)); B[0]=f.x; B[1]=f.y;
        f = __half22float2(*reinterpret_cast<const __half2*>(&kvb.y)); B[2]=f.x; B[3]=f.y;
        f = __half22float2(*reinterpret_cast<const __half2*>(&kvb.z)); B[4]=f.x; B[5]=f.y;
        f = __half22float2(*reinterpret_cast<const __half2*>(&kvb.w)); B[6]=f.x; B[7]=f.y;
    }
    if (half) {  // K' = k o (-e123): {k7, k6, -k5, k4, -k3, k2, -k1, -k0}
        float tA[8], tB[8];
        tA[0]= A[7]; tA[1]= A[6]; tA[2]=-A[5]; tA[3]= A[4];
        tA[4]=-A[3]; tA[5]= A[2]; tA[6]=-A[1]; tA[7]=-A[0];
        tB[0]= B[7]; tB[1]= B[6]; tB[2]=-B[5]; tB[3]= B[4];
        tB[4]=-B[3]; tB[5]= B[2]; tB[6]=-B[1]; tB[7]=-B[0];
#pragma unroll
        for (int i = 0; i < 8; i++) { A[i] = tA[i]; B[i] = tB[i]; }
    }
    const ull K0 = pk2(A[0],B[0]), K1 = pk2(A[1],B[1]), K2 = pk2(A[2],B[2]),
              K3 = pk2(A[3],B[3]), K4 = pk2(A[4],B[4]), K5 = pk2(A[5],B[5]),
              K6 = pk2(A[6],B[6]), K7 = pk2(A[7],B[7]);
    const ull NK1 = pk2(-A[1],-B[1]), NK2 = pk2(-A[2],-B[2]),
              NK4 = pk2(-A[4],-B[4]), NK5 = pk2(-A[5],-B[5]),
              NK6 = pk2(-A[6],-B[6]), NK7 = pk2(-A[7],-B[7]);
    const ull MNEG1 = pk2(-1.0f, -1.0f);

    __syncthreads();

    // float4 index of this thread's first chunk for nl=0
    size_t fi = ((size_t)(b * SEQ + n0) * SEQ + m_a) * 2 + half;
    float4* o4 = reinterpret_cast<float4*>(out);

#pragma unroll 1
    for (int nl = 0; nl < 32; nl++) {
        const float q0 = qs[nl][0], q1 = qs[nl][1], q2 = qs[nl][2], q3 = qs[nl][3];
        const float q4 = qs[nl][4], q5 = qs[nl][5], q6 = qs[nl][6], q7 = qs[nl][7];
        const ull P0 = pk2(q0,q0), P1 = pk2(q1,q1), P2 = pk2(q2,q2), P3 = pk2(q3,q3),
                  P4 = pk2(q4,q4), P5 = pk2(q5,q5), P6 = pk2(q6,q6), P7 = pk2(q7,q7);

        // o0..o3 of q o K (verified table; odd lanes' K is pre-transformed)
        ull a0 = f2mul(P0, K0);
        ull a1 = f2mul(P0, K1);
        ull a2 = f2mul(P0, K2);
        ull a3 = f2mul(P0, K3);
        a0 = f2fma(P1, K1,  a0); a1 = f2fma(P1, K0,  a1); a2 = f2fma(P1, K4,  a2); a3 = f2fma(P1, K5,  a3);
        a0 = f2fma(P2, K2,  a0); a1 = f2fma(P2, NK4, a1); a2 = f2fma(P2, K0,  a2); a3 = f2fma(P2, K6,  a3);
        a0 = f2fma(P3, K3,  a0); a1 = f2fma(P3, NK5, a1); a2 = f2fma(P3, NK6, a2); a3 = f2fma(P3, K0,  a3);
        a0 = f2fma(P4, NK4, a0); a1 = f2fma(P4, K2,  a1); a2 = f2fma(P4, NK1, a2); a3 = f2fma(P4, NK7, a3);
        a0 = f2fma(P5, NK5, a0); a1 = f2fma(P5, K3,  a1); a2 = f2fma(P5, K7,  a2); a3 = f2fma(P5, NK1, a3);
        a0 = f2fma(P6, NK6, a0); a1 = f2fma(P6, NK7, a1); a2 = f2fma(P6, K3,  a2); a3 = f2fma(P6, NK2, a3);
        a0 = f2fma(P7, NK7, a0); a1 = f2fma(P7, NK6, a1); a2 = f2fma(P7, K5,  a2); a3 = f2fma(P7, NK4, a3);

        // odd lanes: (out4,out5,out6,out7) = (o3, -o2, o1, o0)
        const ull na2 = f2mul(a2, MNEG1);
        const ull s0 = half ? a3  : a0;
        const ull s1 = half ? na2 : a1;
        const ull s2 = half ? a1  : a2;
        const ull s3 = half ? a0  : a3;

        float e0,e1,e2,e3, f0,f1,f2,f3;
        upk2(s0, e0, f0); upk2(s1, e1, f1); upk2(s2, e2, f2); upk2(s3, e3, f3);

        __stcs(&o4[fi],      make_float4(e0, e1, e2, e3));   // m_a
        __stcs(&o4[fi + 32], make_float4(f0, f1, f2, f3));   // m_a + 16
        fi += 2048;   // next n row
    }
}

extern "C" void kernel_launch(void* const* d_in, const int* in_sizes, int n_in,
                              void* d_out, int out_size)
{
    (void)in_sizes; (void)n_in; (void)out_size;
    const float* x     = (const float*)d_in[0];
    const float* Wq    = (const float*)d_in[1];
    const float* bq    = (const float*)d_in[2];
    const float* Wk    = (const float*)d_in[3];
    const float* bk    = (const float*)d_in[4];
    const float* gamma = (const float*)d_in[5];
    const float* beta  = (const float*)d_in[6];
    float* out = (float*)d_out;

    proj_ln_kernel<<<1024, 256>>>(x, Wq, bq, Wk, bk, gamma, beta);
    gp_kernel<<<dim3(128, 4), 256>>>(out);
}

// round 6
// speedup vs baseline: 1.9686x; 1.0082x over previous
#include <cuda_runtime.h>
#include <cuda_fp16.h>
#include <cstdint>

#define SEQ 1024

// fp16 q/k scratch (allocation-free: __device__ globals)
__device__ __half q_buf[4 * SEQ * 8];
__device__ __half k_buf[4 * SEQ * 8];
// partial-sum scratch: [half][n][proj][b][8 comps]
__device__ float part_buf[2 * SEQ * 2 * 4 * 8];

typedef unsigned long long ull;

// ---- packed f32x2 helpers (Blackwell) ----
__device__ __forceinline__ ull pk2(float lo, float hi) {
    ull d;
    asm("mov.b64 %0, {%1, %2};" : "=l"(d)
        : "r"(__float_as_uint(lo)), "r"(__float_as_uint(hi)));
    return d;
}
__device__ __forceinline__ void upk2(ull d, float& lo, float& hi) {
    unsigned a, b;
    asm("mov.b64 {%0, %1}, %2;" : "=r"(a), "=r"(b) : "l"(d));
    lo = __uint_as_float(a); hi = __uint_as_float(b);
}
__device__ __forceinline__ ull f2fma(ull a, ull b, ull c) {
    ull d;
    asm("fma.rn.f32x2 %0, %1, %2, %3;" : "=l"(d) : "l"(a), "l"(b), "l"(c));
    return d;
}
__device__ __forceinline__ ull f2mul(ull a, ull b) {
    ull d;
    asm("mul.rn.f32x2 %0, %1, %2;" : "=l"(d) : "l"(a), "l"(b));
    return d;
}

// ---------------------------------------------------------------------------
// Kernel A1: partial mvlinear for one (n, m-half). 4 warps = m-eighths of the
// half (128 m each, 4 iters). q AND k share the x loads. Butterfly transpose-
// reduce; block writes 64 partial sums ({proj} x {b} x {8}) to part_buf.
// ---------------------------------------------------------------------------
__global__ void __launch_bounds__(128) proj_partial_kernel(
    const float* __restrict__ x,     // [4,1024,8]
    const float* __restrict__ Wq,    // [1024,1024,4]
    const float* __restrict__ Wk)    // [1024,1024,4]
{
    __shared__ float sred[4][64];

    const int w    = threadIdx.x >> 5;
    const int lane = threadIdx.x & 31;
    const int n    = blockIdx.x;
    const int half = blockIdx.y;

    const float4* wqr = reinterpret_cast<const float4*>(Wq) + (size_t)n * SEQ;
    const float4* wkr = reinterpret_cast<const float4*>(Wk) + (size_t)n * SEQ;
    const float4* x4  = reinterpret_cast<const float4*>(x);

    float aq[32], ak[32];
#pragma unroll
    for (int v = 0; v < 32; v++) { aq[v] = 0.0f; ak[v] = 0.0f; }

    const int mbase = half * 512 + w * 128 + lane;
#pragma unroll
    for (int mi = 0; mi < 4; mi++) {
        const int m = mbase + mi * 32;
        const float4 wq = __ldg(&wqr[m]);
        const float4 wk = __ldg(&wkr[m]);
#pragma unroll
        for (int b = 0; b < 4; b++) {
            const float4 x0 = __ldg(&x4[(b * SEQ + m) * 2]);
            const float4 x1 = __ldg(&x4[(b * SEQ + m) * 2 + 1]);
            aq[b*8+0] = fmaf(wq.x, x0.x, aq[b*8+0]);  ak[b*8+0] = fmaf(wk.x, x0.x, ak[b*8+0]);
            aq[b*8+1] = fmaf(wq.y, x0.y, aq[b*8+1]);  ak[b*8+1] = fmaf(wk.y, x0.y, ak[b*8+1]);
            aq[b*8+2] = fmaf(wq.y, x0.z, aq[b*8+2]);  ak[b*8+2] = fmaf(wk.y, x0.z, ak[b*8+2]);
            aq[b*8+3] = fmaf(wq.y, x0.w, aq[b*8+3]);  ak[b*8+3] = fmaf(wk.y, x0.w, ak[b*8+3]);
            aq[b*8+4] = fmaf(wq.z, x1.x, aq[b*8+4]);  ak[b*8+4] = fmaf(wk.z, x1.x, ak[b*8+4]);
            aq[b*8+5] = fmaf(wq.z, x1.y, aq[b*8+5]);  ak[b*8+5] = fmaf(wk.z, x1.y, ak[b*8+5]);
            aq[b*8+6] = fmaf(wq.z, x1.z, aq[b*8+6]);  ak[b*8+6] = fmaf(wk.z, x1.z, ak[b*8+6]);
            aq[b*8+7] = fmaf(wq.w, x1.w, aq[b*8+7]);  ak[b*8+7] = fmaf(wk.w, x1.w, ak[b*8+7]);
        }
    }

    // Butterfly transpose-reduce (x2): lane l ends holding value index l
    // (b = l>>3, comp = l&7).
#pragma unroll
    for (int off = 16; off; off >>= 1) {
        const bool up = (lane & off) != 0;
#pragma unroll
        for (int k = 0; k < off; k++) {
            float sq = up ? aq[k] : aq[k + off];
            float oq = __shfl_xor_sync(0xffffffffu, sq, off);
            aq[k] = (up ? aq[k + off] : aq[k]) + oq;
            float sk = up ? ak[k] : ak[k + off];
            float ok = __shfl_xor_sync(0xffffffffu, sk, off);
            ak[k] = (up ? ak[k + off] : ak[k]) + ok;
        }
    }
    sred[w][lane]      = aq[0];
    sred[w][lane + 32] = ak[0];
    __syncthreads();

    const int t = threadIdx.x;
    if (t < 8) {
        const int b  = t & 3;
        const int pj = (t >> 2) & 1;
        float* dst = part_buf + (((size_t)half * SEQ + n) * 2 + pj) * 32 + b * 8;
#pragma unroll
        for (int i = 0; i < 8; i++) {
            const int c = pj * 32 + b * 8 + i;
            dst[i] = (sred[0][c] + sred[1][c]) + (sred[2][c] + sred[3][c]);
        }
    }
}

// ---------------------------------------------------------------------------
// Kernel A2: combine the two m-half partials, add bias, LayerNorm, fp16 cast.
// One thread per (n, proj, b) = 8192 threads.
// ---------------------------------------------------------------------------
__global__ void __launch_bounds__(256) ln_finalize_kernel(
    const float* __restrict__ bq,
    const float* __restrict__ bk,
    const float* __restrict__ gamma,
    const float* __restrict__ beta)
{
    const int t  = blockIdx.x * 256 + threadIdx.x;
    const int n  = t >> 3;
    const int pj = (t >> 2) & 1;
    const int b  = t & 3;

    const float* p0 = part_buf + (((size_t)0 * SEQ + n) * 2 + pj) * 32 + b * 8;
    const float* p1 = part_buf + (((size_t)1 * SEQ + n) * 2 + pj) * 32 + b * 8;

    float v[8];
#pragma unroll
    for (int i = 0; i < 8; i++) v[i] = p0[i] + p1[i];
    v[0] += pj ? bk[n] : bq[n];   // bias on scalar comp, before LN

    float mu = 0.0f;
#pragma unroll
    for (int i = 0; i < 8; i++) mu += v[i];
    mu *= 0.125f;
    float var = 0.0f;
#pragma unroll
    for (int i = 0; i < 8; i++) { float d = v[i] - mu; var = fmaf(d, d, var); }
    const float r = rsqrtf(var * 0.125f + 1e-5f);

    __half2* dst = reinterpret_cast<__half2*>(
        (pj ? k_buf : q_buf) + ((size_t)b * SEQ + n) * 8);
#pragma unroll
    for (int j = 0; j < 4; j++) {
        float a0 = (v[2*j]   - mu) * r * gamma[2*j]   + beta[2*j];
        float a1 = (v[2*j+1] - mu) * r * gamma[2*j+1] + beta[2*j+1];
        dst[j] = __floats2half2_rn(a0, a1);
    }
}

// ---------------------------------------------------------------------------
// Kernel B: geometric product out[b,n,m,:] = GP(q[b,n], k[b,m]), Cl(3,0),
// basis [1, e1, e2, e3, e12, e13, e23, e123].
// Even lanes compute comps 0..3, odd lanes comps 4..7 via duality
// out o (-e123) (K pre-transformed by a signed permutation; identical FMA
// table; order un-reversed at store). Thread covers m-pair (m_a, m_a+16)
// in f32x2 lanes; each warp-STG is 512B contiguous. 16 n-rows per block,
// q tile pre-packed as (q,q) ulls in smem -> per-nl broadcast LDS.64,
// no packing movs. 2048 blocks for occupancy.
// ---------------------------------------------------------------------------
__global__ void __launch_bounds__(256) gp_kernel(float* __restrict__ out)
{
    __shared__ ull qsp[16][8];

    const int b      = blockIdx.y;
    const int ntile  = blockIdx.x >> 2;     // 0..63
    const int mchunk = blockIdx.x & 3;      // 0..3
    const int n0     = ntile * 16;
    const int t      = threadIdx.x;
    const int w      = t >> 5;
    const int lane   = t & 31;
    const int half   = lane & 1;            // 0: comps 0-3, 1: comps 4-7
    const int mm     = lane >> 1;           // 0..15
    const int m_a    = mchunk * 256 + w * 32 + mm;   // pair partner: m_a + 16

    // q tile: 16 rows x 8 comps, stored duplicated-packed for direct LDS.64
    if (t < 128) {
        const float v = __half2float(
            q_buf[((size_t)b * SEQ + n0 + (t >> 3)) * 8 + (t & 7)]);
        qsp[t >> 3][t & 7] = pk2(v, v);
    }

    // K for both m's of this thread
    const uint4* kb4 = reinterpret_cast<const uint4*>(k_buf) + (size_t)b * SEQ;
    const uint4 kva = __ldg(&kb4[m_a]);
    const uint4 kvb = __ldg(&kb4[m_a + 16]);

    float A[8], B[8];
    {
        float2 f;
        f = __half22float2(*reinterpret_cast<const __half2*>(&kva.x)); A[0]=f.x; A[1]=f.y;
        f = __half22float2(*reinterpret_cast<const __half2*>(&kva.y)); A[2]=f.x; A[3]=f.y;
        f = __half22float2(*reinterpret_cast<const __half2*>(&kva.z)); A[4]=f.x; A[5]=f.y;
        f = __half22float2(*reinterpret_cast<const __half2*>(&kva.w)); A[6]=f.x; A[7]=f.y;
        f = __half22float2(*reinterpret_cast<const __half2*>(&kvb.x)); B[0]=f.x; B[1]=f.y;
        f = __half22float2(*reinterpret_cast<const __half2*>(&kvb.y)); B[2]=f.x; B[3]=f.y;
        f = __half22float2(*reinterpret_cast<const __half2*>(&kvb.z)); B[4]=f.x; B[5]=f.y;
        f = __half22float2(*reinterpret_cast<const __half2*>(&kvb.w)); B[6]=f.x; B[7]=f.y;
    }
    if (half) {  // K' = k o (-e123): {k7, k6, -k5, k4, -k3, k2, -k1, -k0}
        float tA[8], tB[8];
        tA[0]= A[7]; tA[1]= A[6]; tA[2]=-A[5]; tA[3]= A[4];
        tA[4]=-A[3]; tA[5]= A[2]; tA[6]=-A[1]; tA[7]=-A[0];
        tB[0]= B[7]; tB[1]= B[6]; tB[2]=-B[5]; tB[3]= B[4];
        tB[4]=-B[3]; tB[5]= B[2]; tB[6]=-B[1]; tB[7]=-B[0];
#pragma unroll
        for (int i = 0; i < 8; i++) { A[i] = tA[i]; B[i] = tB[i]; }
    }
    const ull K0 = pk2(A[0],B[0]), K1 = pk2(A[1],B[1]), K2 = pk2(A[2],B[2]),
              K3 = pk2(A[3],B[3]), K4 = pk2(A[4],B[4]), K5 = pk2(A[5],B[5]),
              K6 = pk2(A[6],B[6]), K7 = pk2(A[7],B[7]);
    const ull NK1 = pk2(-A[1],-B[1]), NK2 = pk2(-A[2],-B[2]),
              NK4 = pk2(-A[4],-B[4]), NK5 = pk2(-A[5],-B[5]),
              NK6 = pk2(-A[6],-B[6]), NK7 = pk2(-A[7],-B[7]);
    const ull MNEG1 = pk2(-1.0f, -1.0f);

    __syncthreads();

    // float4 index of this thread's first chunk for nl=0
    size_t fi = ((size_t)(b * SEQ + n0) * SEQ + m_a) * 2 + half;
    float4* o4 = reinterpret_cast<float4*>(out);

#pragma unroll 1
    for (int nl = 0; nl < 16; nl++) {
        const ull P0 = qsp[nl][0], P1 = qsp[nl][1], P2 = qsp[nl][2], P3 = qsp[nl][3],
                  P4 = qsp[nl][4], P5 = qsp[nl][5], P6 = qsp[nl][6], P7 = qsp[nl][7];

        // o0..o3 of q o K (verified table; odd lanes' K is pre-transformed)
        ull a0 = f2mul(P0, K0);
        ull a1 = f2mul(P0, K1);
        ull a2 = f2mul(P0, K2);
        ull a3 = f2mul(P0, K3);
        a0 = f2fma(P1, K1,  a0); a1 = f2fma(P1, K0,  a1); a2 = f2fma(P1, K4,  a2); a3 = f2fma(P1, K5,  a3);
        a0 = f2fma(P2, K2,  a0); a1 = f2fma(P2, NK4, a1); a2 = f2fma(P2, K0,  a2); a3 = f2fma(P2, K6,  a3);
        a0 = f2fma(P3, K3,  a0); a1 = f2fma(P3, NK5, a1); a2 = f2fma(P3, NK6, a2); a3 = f2fma(P3, K0,  a3);
        a0 = f2fma(P4, NK4, a0); a1 = f2fma(P4, K2,  a1); a2 = f2fma(P4, NK1, a2); a3 = f2fma(P4, NK7, a3);
        a0 = f2fma(P5, NK5, a0); a1 = f2fma(P5, K3,  a1); a2 = f2fma(P5, K7,  a2); a3 = f2fma(P5, NK1, a3);
        a0 = f2fma(P6, NK6, a0); a1 = f2fma(P6, NK7, a1); a2 = f2fma(P6, K3,  a2); a3 = f2fma(P6, NK2, a3);
        a0 = f2fma(P7, NK7, a0); a1 = f2fma(P7, NK6, a1); a2 = f2fma(P7, K5,  a2); a3 = f2fma(P7, NK4, a3);

        // odd lanes: (out4,out5,out6,out7) = (o3, -o2, o1, o0)
        const ull na2 = f2mul(a2, MNEG1);
        const ull s0 = half ? a3  : a0;
        const ull s1 = half ? na2 : a1;
        const ull s2 = half ? a1  : a2;
        const ull s3 = half ? a0  : a3;

        float e0,e1,e2,e3, f0,f1,f2,f3;
        upk2(s0, e0, f0); upk2(s1, e1, f1); upk2(s2, e2, f2); upk2(s3, e3, f3);

        __stcs(&o4[fi],      make_float4(e0, e1, e2, e3));   // m_a
        __stcs(&o4[fi + 32], make_float4(f0, f1, f2, f3));   // m_a + 16
        fi += 2048;   // next n row
    }
}

extern "C" void kernel_launch(void* const* d_in, const int* in_sizes, int n_in,
                              void* d_out, int out_size)
{
    (void)in_sizes; (void)n_in; (void)out_size;
    const float* x     = (const float*)d_in[0];
    const float* Wq    = (const float*)d_in[1];
    const float* bq    = (const float*)d_in[2];
    const float* Wk    = (const float*)d_in[3];
    const float* bk    = (const float*)d_in[4];
    const float* gamma = (const float*)d_in[5];
    const float* beta  = (const float*)d_in[6];
    float* out = (float*)d_out;

    proj_partial_kernel<<<dim3(1024, 2), 128>>>(x, Wq, Wk);
    ln_finalize_kernel<<<32, 256>>>(bq, bk, gamma, beta);
    gp_kernel<<<dim3(256, 4), 256>>>(out);
}